// round 2
// baseline (speedup 1.0000x reference)
#include <cuda_runtime.h>
#include <cuda_bf16.h>

#define N_TOK   65536
#define KCODES  8192
#define DIM     64
#define MT      128
#define KT      128
#define ZQ_ELEMS 4194304   // 16*64*64*64
#define SMEMB   ((2*DIM*MT + MT)*4)

// scratch (static __device__ allocations are allowed)
__device__ float g_ET[DIM*KCODES];   // embedding transposed [d][k], 2MB (L2 resident)
__device__ float g_enorm[KCODES];
__device__ int   g_idx[N_TOK];
__device__ float g_loss;

// ---------------------------------------------------------------------------
// K1: transpose embedding -> g_ET, compute ||e_k||^2, zero loss accumulator
// ---------------------------------------------------------------------------
__global__ void vq_pre(const float* __restrict__ emb){
    __shared__ float tile[64][65];
    int k0 = blockIdx.x * 64;
    int tid = threadIdx.x;
    for (int i = tid; i < 64*64; i += 256){
        int k = i >> 6, d = i & 63;
        tile[k][d] = emb[(k0 + k)*64 + d];
    }
    __syncthreads();
    for (int i = tid; i < 64*64; i += 256){
        int d = i >> 6, k = i & 63;
        g_ET[d*KCODES + k0 + k] = tile[k][d];
    }
    if (tid < 64){
        float s = 0.f;
        #pragma unroll
        for (int d = 0; d < 64; d++){ float v = tile[tid][d]; s = fmaf(v, v, s); }
        g_enorm[k0 + tid] = s;
    }
    if (blockIdx.x == 0 && tid == 0) g_loss = 0.f;
}

// ---------------------------------------------------------------------------
// K2: main distance + argmin. Block: 128 rows x all 8192 codes (K chunked 128).
// Thread micro-tile 8x8 (split 4+4 fragments for conflict-free LDS.128).
// Replicates reference rounding: d = fl( fl(znorm + enorm_k) - 2*dot ).
// First-occurrence tie-break (strict <, cross-thread tie -> lower index).
// ---------------------------------------------------------------------------
__global__ __launch_bounds__(256, 2) void vq_main(const float* __restrict__ z,
                                                  float* __restrict__ outIdxF,
                                                  int writeF){
    extern __shared__ float sm[];
    float* Zs  = sm;                // [64][128]
    float* Es  = sm + DIM*MT;       // [64][128]
    float* znS = sm + 2*DIM*MT;     // [128]

    int tid = threadIdx.x;
    int tx = tid & 15, ty = tid >> 4;
    int n0 = blockIdx.x * MT;
    const float* zb = z + (n0 >> 12) * (DIM*4096) + (n0 & 4095);

    // load Z tile transposed: Zs[c][m] = z[b][c][hw0+m]  (gmem coalesced along m)
    for (int i = tid; i < DIM*MT; i += 256)
        Zs[i] = zb[(i >> 7) * 4096 + (i & 127)];
    __syncthreads();

    if (tid < MT){
        float s = 0.f;
        #pragma unroll
        for (int d = 0; d < DIM; d++){ float v = Zs[d*MT + tid]; s = fmaf(v, v, s); }
        znS[tid] = s;
    }
    __syncthreads();

    float zn[8];
    #pragma unroll
    for (int r = 0; r < 8; r++) zn[r] = znS[((r >> 2) << 6) + ty*4 + (r & 3)];

    float bestd[8]; int besti[8];
    #pragma unroll
    for (int r = 0; r < 8; r++){ bestd[r] = 3.402823e38f; besti[r] = 0; }

    for (int k0 = 0; k0 < KCODES; k0 += KT){
        __syncthreads();
        for (int i = tid; i < DIM*KT; i += 256)
            Es[i] = g_ET[(i >> 7)*KCODES + k0 + (i & 127)];
        __syncthreads();

        float acc[8][8];
        #pragma unroll
        for (int a = 0; a < 8; a++)
            #pragma unroll
            for (int b2 = 0; b2 < 8; b2++) acc[a][b2] = 0.f;

        #pragma unroll 8
        for (int d = 0; d < DIM; d++){
            float4 za  = *(const float4*)&Zs[d*MT + ty*4];
            float4 zb4 = *(const float4*)&Zs[d*MT + 64 + ty*4];
            float4 ea  = *(const float4*)&Es[d*KT + tx*4];
            float4 eb  = *(const float4*)&Es[d*KT + 64 + tx*4];
            float zf[8] = {za.x, za.y, za.z, za.w, zb4.x, zb4.y, zb4.z, zb4.w};
            float ef[8] = {ea.x, ea.y, ea.z, ea.w, eb.x, eb.y, eb.z, eb.w};
            #pragma unroll
            for (int r = 0; r < 8; r++)
                #pragma unroll
                for (int c = 0; c < 8; c++)
                    acc[r][c] = fmaf(zf[r], ef[c], acc[r][c]);
        }

        // epilogue: ascending code order within thread -> strict < keeps first
        #pragma unroll
        for (int c = 0; c < 8; c++){
            int kk = k0 + ((c >> 2) << 6) + tx*4 + (c & 3);
            float en = __ldg(&g_enorm[kk]);
            #pragma unroll
            for (int r = 0; r < 8; r++){
                float t2 = zn[r] + en;                    // fl(zn + en)
                float dd = fmaf(-2.f, acc[r][c], t2);     // fl(t2 - 2*dot), single rounding
                if (dd < bestd[r]){ bestd[r] = dd; besti[r] = kk; }
            }
        }
    }

    // cross-thread reduce per row (tie -> lower index = first occurrence)
    __syncthreads();
    float* bdS = Zs;            // reuse: [16][128]
    int*   biS = (int*)Es;
    #pragma unroll
    for (int r = 0; r < 8; r++){
        int row = ((r >> 2) << 6) + ty*4 + (r & 3);
        bdS[tx*MT + row] = bestd[r];
        biS[tx*MT + row] = besti[r];
    }
    __syncthreads();
    if (tid < MT){
        float bd = bdS[tid]; int bi = biS[tid];
        #pragma unroll
        for (int t = 1; t < 16; t++){
            float d2 = bdS[t*MT + tid]; int i2 = biS[t*MT + tid];
            if (d2 < bd || (d2 == bd && i2 < bi)){ bd = d2; bi = i2; }
        }
        g_idx[n0 + tid] = bi;
        if (writeF) outIdxF[n0 + tid] = (float)bi;
    }
}

// ---------------------------------------------------------------------------
// K3: gather z_q, straight-through output z + (e - z), transpose back, loss
// ---------------------------------------------------------------------------
__global__ void vq_out(const float* __restrict__ z, const float* __restrict__ emb,
                       float* __restrict__ outz){
    int tid = threadIdx.x;
    int n0 = blockIdx.x * 64;
    const int b = n0 >> 12; const int hw0 = n0 & 4095;
    const float* zb = z    + b*(64*4096) + hw0;
    float*       ob = outz + b*(64*4096) + hw0;

    __shared__ int idxs[64];
    if (tid < 64) idxs[tid] = g_idx[n0 + tid];
    __syncthreads();

    float ls = 0.f;
    for (int i = tid; i < 64*64; i += 256){
        int c = i >> 6, m = i & 63;
        float e  = __ldg(&emb[idxs[m]*64 + c]);
        float zv = zb[c*4096 + m];
        float t  = e - zv;              // fl(zq - zc)
        ob[c*4096 + m] = zv + t;        // fl(zc + fl(zq - zc)) — STE rounding replicated
        ls = fmaf(t, t, ls);
    }

    __shared__ float red[256];
    red[tid] = ls; __syncthreads();
    for (int s = 128; s > 0; s >>= 1){
        if (tid < s) red[tid] += red[tid + s];
        __syncthreads();
    }
    if (tid == 0) atomicAdd(&g_loss, red[0]);
}

// ---------------------------------------------------------------------------
// K4: finalize loss = mean + 0.25*mean
// ---------------------------------------------------------------------------
__global__ void vq_fin(float* __restrict__ out, int full){
    if (full){
        float m = g_loss * (1.f / (float)ZQ_ELEMS);
        out[ZQ_ELEMS] = m + 0.25f * m;
    }
}

// ---------------------------------------------------------------------------
extern "C" void kernel_launch(void* const* d_in, const int* in_sizes, int n_in,
                              void* d_out, int out_size){
    const float* z   = (const float*)d_in[0];
    const float* emb = (const float*)d_in[1];
    float* out = (float*)d_out;

    // output layout: [ z_q (4194304) | loss (1) | indices (65536) ] as float32
    int full = (out_size >= ZQ_ELEMS + 1 + N_TOK) ? 1 : 0;

    cudaFuncSetAttribute(vq_main, cudaFuncAttributeMaxDynamicSharedMemorySize, SMEMB);

    vq_pre<<<KCODES/64, 256>>>(emb);
    vq_main<<<N_TOK/MT, 256, SMEMB>>>(z, full ? (out + ZQ_ELEMS + 1) : out, full);
    vq_out<<<N_TOK/64, 256>>>(z, emb, out);
    vq_fin<<<1, 1>>>(out, full);
}

// round 4
// speedup vs baseline: 1.0545x; 1.0545x over previous
#include <cuda_runtime.h>
#include <cstdint>

#define N_TOK    65536
#define KCODES   8192
#define DIM      64
#define ZQ_ELEMS 4194304     // 16*64*64*64
#define NT       256         // 8 warps
#define NCH      64          // 4096 codes per half / 64 per chunk
#define TH       1e-4f

// ---- dynamic smem layout (bytes) ----
#define SOFF_AP   0          // 65536 : A frags [w8][ks8][spl2][lane32][r4] fp32(tf32)
#define SOFF_BP   65536      // 65536 : B frags [buf2][nt8][ks8][spl2][lane32][slot2]
#define SOFF_EN   131072     // 2*64*4
#define SOFF_ZN   131584     // 128*4
#define SMEM_SZ   132096
// staging for z tile reuses the BP region (64*132*4 = 33792 <= 65536)

__device__ float              g_enorm[KCODES];
__device__ unsigned long long g_best[N_TOK];
__device__ float              g_loss;

__device__ __forceinline__ uint32_t tf32_rna(float v){
    uint32_t r; asm("cvt.rna.tf32.f32 %0, %1;" : "=r"(r) : "f"(v)); return r;
}
__device__ __forceinline__ void split_tf32(float v, uint32_t& hb, uint32_t& lb){
    hb = tf32_rna(v);
    lb = tf32_rna(v - __uint_as_float(hb));
}
__device__ __forceinline__ void mma_tf32(float* d, const uint32_t* a, const uint32_t* b){
    asm volatile("mma.sync.aligned.m16n8k8.row.col.f32.tf32.tf32.f32 "
        "{%0,%1,%2,%3}, {%4,%5,%6,%7}, {%8,%9}, {%0,%1,%2,%3};"
        : "+f"(d[0]), "+f"(d[1]), "+f"(d[2]), "+f"(d[3])
        : "r"(a[0]), "r"(a[1]), "r"(a[2]), "r"(a[3]), "r"(b[0]), "r"(b[1]));
}
__device__ __forceinline__ unsigned long long packbi(float dd, int idx){
    uint32_t u = __float_as_uint(dd);
    u = (u & 0x80000000u) ? ~u : (u | 0x80000000u);
    return ((unsigned long long)u << 32) | (uint32_t)idx;
}
// exact distance, replicating the validated R2 arithmetic bit-for-bit:
// sequential fmaf over d ascending; dd = fmaf(-2, dot, fl(zn+en))
__device__ float exact_dd(const float* __restrict__ z, const float* __restrict__ emb,
                          int tok, int k, float zn){
    int b = tok >> 12, hw = tok & 4095;
    const float* zp = z + b*262144 + hw;
    const float* ep = emb + k*64;
    float dot = 0.f;
    #pragma unroll
    for (int d = 0; d < 64; d++) dot = fmaf(__ldg(zp + d*4096), __ldg(ep + d), dot);
    float t2 = zn + __ldg(&g_enorm[k]);
    return fmaf(-2.f, dot, t2);
}

// ---------------------------------------------------------------------------
// K1: ||e_k||^2, init g_best, zero loss
// ---------------------------------------------------------------------------
__global__ void vq_pre(const float* __restrict__ emb){
    int t = blockIdx.x * 256 + threadIdx.x;
    if (t < KCODES){
        const float4* r = (const float4*)(emb + t*64);
        float s = 0.f;
        #pragma unroll
        for (int i = 0; i < 16; i++){
            float4 v = __ldg(&r[i]);
            s = fmaf(v.x,v.x,s); s = fmaf(v.y,v.y,s); s = fmaf(v.z,v.z,s); s = fmaf(v.w,v.w,s);
        }
        g_enorm[t] = s;
    }
    if (t < N_TOK) g_best[t] = 0xFFFFFFFFFFFFFFFFull;
    if (t == 0) g_loss = 0.f;
}

// ---------------------------------------------------------------------------
// K2: 3xTF32 mma.sync distance + top-2 argmin + exact rescore + atomic merge
// grid: (512 token tiles, 2 code halves); CTA = 128 tokens x 4096 codes
// ---------------------------------------------------------------------------
__global__ __launch_bounds__(NT, 1) void vq_main(const float* __restrict__ z,
                                                 const float* __restrict__ emb){
    extern __shared__ __align__(16) char smem[];
    float*    Ap  = (float*)(smem + SOFF_AP);
    float*    Bp  = (float*)(smem + SOFF_BP);
    float*    enS = (float*)(smem + SOFF_EN);
    float*    znS = (float*)(smem + SOFF_ZN);
    float*    stage = (float*)(smem + SOFF_BP);   // [64][132], pre-loop only

    int tid = threadIdx.x, wid = tid >> 5, lane = tid & 31;
    int n0 = blockIdx.x * 128;
    int kbase = blockIdx.y * 4096;
    const float* zb = z + (n0 >> 12) * 262144 + (n0 & 4095);

    // ---- stage z tile [d][m] (coalesced) ----
    for (int i = tid; i < 64*128; i += NT){
        int d = i >> 7, m = i & 127;
        stage[d*132 + m] = zb[d*4096 + m];
    }
    __syncthreads();
    // ---- zn (sequential fmaf d ascending — matches reference/R2) ----
    if (tid < 128){
        float s = 0.f;
        #pragma unroll
        for (int d = 0; d < 64; d++){ float v = stage[d*132 + tid]; s = fmaf(v, v, s); }
        znS[tid] = s;
    }
    __syncthreads();
    // ---- build A fragments (permuted, fragment-linear) ----
    // idx -> w, ks, spl, l, r ;  m = w*16 + l/4 + (r&1)*8 ; k = ks*8 + l%4 + ((r>>1)&1)*4
    for (int idx = tid; idx < 16384; idx += NT){
        int w = idx >> 11, rem = idx & 2047;
        int r = rem & 3, q = rem >> 2;
        int l = q & 31, p = q >> 5;
        int spl = p & 1, ks = p >> 1;
        int m = w*16 + (l >> 2) + (r & 1)*8;
        int k = ks*8 + (l & 3) + ((r >> 1) & 1)*4;
        float v = stage[k*132 + m];
        uint32_t hb = tf32_rna(v);
        uint32_t out = spl ? tf32_rna(v - __uint_as_float(hb)) : hb;
        // NOTE: stage overlaps Bp; A writes must not race stage reads of other threads
        ((uint32_t*)&Ap[0])[idx] = out;
    }
    __syncthreads();

    const float4* embc = (const float4*)emb;
    float zn0 = znS[wid*16 + (lane >> 2)];
    float zn1 = znS[wid*16 + (lane >> 2) + 8];

    // ---- B producer helper (inline) ----
    // chunk c -> buffer b. thread covers 4 float4 (16 elems), each elem -> hi/lo STS
    auto produce = [&](int c, int b){
        #pragma unroll
        for (int j = 0; j < 4; j++){
            int f = j*256 + tid;                       // float4 index in chunk
            float4 v = __ldg(&embc[(kbase + c*64)*16 + f]);
            int n = f >> 4, k0 = (f & 15) * 4;
            float vv[4] = {v.x, v.y, v.z, v.w};
            #pragma unroll
            for (int e = 0; e < 4; e++){
                int k = k0 + e;
                int nt = n >> 3, g = n & 7, ks = k >> 3, krel = k & 7;
                int t4 = krel & 3, slot = krel >> 2;
                int l = g*4 + t4;
                uint32_t hb, lb; split_tf32(vv[e], hb, lb);
                int w0 = b*8192 + (((nt*8 + ks)*2 + 0)*32 + l)*2 + slot;
                int w1 = b*8192 + (((nt*8 + ks)*2 + 1)*32 + l)*2 + slot;
                ((uint32_t*)Bp)[w0] = hb;
                ((uint32_t*)Bp)[w1] = lb;
            }
        }
        if (tid < 64) enS[b*64 + tid] = __ldg(&g_enorm[kbase + c*64 + tid]);
    };

    produce(0, 0);
    __syncthreads();

    float b1_0 = 3.402823e38f, b2_0 = 3.402823e38f;
    float b1_1 = 3.402823e38f, b2_1 = 3.402823e38f;
    int   i1_0 = 0, i2_0 = 0, i1_1 = 0, i2_1 = 0;

    #pragma unroll 1
    for (int c = 0; c < NCH; c++){
        int buf = c & 1;
        // prefetch next chunk into registers
        float4 pv[4];
        if (c + 1 < NCH){
            #pragma unroll
            for (int j = 0; j < 4; j++)
                pv[j] = __ldg(&embc[(kbase + (c+1)*64)*16 + j*256 + tid]);
        }

        // ---- mma over this chunk ----
        float acc[8][4];
        #pragma unroll
        for (int nt = 0; nt < 8; nt++){ acc[nt][0]=0.f; acc[nt][1]=0.f; acc[nt][2]=0.f; acc[nt][3]=0.f; }

        #pragma unroll
        for (int ks = 0; ks < 8; ks++){
            uint4 ah = *(const uint4*)&Ap[(wid*2048) + ((ks*2 + 0)*32 + lane)*4];
            uint4 al = *(const uint4*)&Ap[(wid*2048) + ((ks*2 + 1)*32 + lane)*4];
            #pragma unroll
            for (int nt = 0; nt < 8; nt++){
                uint2 bh = *(const uint2*)&Bp[buf*8192 + (((nt*8 + ks)*2 + 0)*32 + lane)*2];
                uint2 bl = *(const uint2*)&Bp[buf*8192 + (((nt*8 + ks)*2 + 1)*32 + lane)*2];
                mma_tf32(acc[nt], (const uint32_t*)&ah, (const uint32_t*)&bl);
                mma_tf32(acc[nt], (const uint32_t*)&al, (const uint32_t*)&bh);
                mma_tf32(acc[nt], (const uint32_t*)&ah, (const uint32_t*)&bh);
            }
        }

        // ---- epilogue: dd + top-2 update (ascending k within thread) ----
        int kb = kbase + c*64;
        #pragma unroll
        for (int nt = 0; nt < 8; nt++){
            #pragma unroll
            for (int e = 0; e < 2; e++){
                int col = nt*8 + (lane & 3)*2 + e;
                float en = enS[buf*64 + col];
                int kk = kb + col;
                float dd0 = fmaf(-2.f, acc[nt][e],     zn0 + en);
                float dd1 = fmaf(-2.f, acc[nt][e + 2], zn1 + en);
                if (dd0 < b1_0){ b2_0=b1_0; i2_0=i1_0; b1_0=dd0; i1_0=kk; }
                else if (dd0 < b2_0){ b2_0=dd0; i2_0=kk; }
                if (dd1 < b1_1){ b2_1=b1_1; i2_1=i1_1; b1_1=dd1; i1_1=kk; }
                else if (dd1 < b2_1){ b2_1=dd1; i2_1=kk; }
            }
        }

        // ---- store prefetched chunk into other buffer ----
        if (c + 1 < NCH){
            #pragma unroll
            for (int j = 0; j < 4; j++){
                int f = j*256 + tid;
                int n = f >> 4, k0 = (f & 15)*4;
                float vv[4] = {pv[j].x, pv[j].y, pv[j].z, pv[j].w};
                #pragma unroll
                for (int e = 0; e < 4; e++){
                    int k = k0 + e;
                    int nt = n >> 3, g = n & 7, ks = k >> 3, krel = k & 7;
                    int t4 = krel & 3, slot = krel >> 2;
                    int l = g*4 + t4;
                    uint32_t hb, lb; split_tf32(vv[e], hb, lb);
                    ((uint32_t*)Bp)[(buf^1)*8192 + (((nt*8+ks)*2+0)*32 + l)*2 + slot] = hb;
                    ((uint32_t*)Bp)[(buf^1)*8192 + (((nt*8+ks)*2+1)*32 + l)*2 + slot] = lb;
                }
            }
            if (tid < 64) enS[(buf^1)*64 + tid] = __ldg(&g_enorm[kbase + (c+1)*64 + tid]);
        }
        __syncthreads();
    }

    // ---- cross-thread top-2 merge within quad (rows owned by 4 lanes) ----
    #pragma unroll
    for (int off = 1; off <= 2; off <<= 1){
        float c1, c2; int ci1, ci2;
        // row 0 set
        c1 = __shfl_xor_sync(0xFFFFFFFF, b1_0, off); ci1 = __shfl_xor_sync(0xFFFFFFFF, i1_0, off);
        c2 = __shfl_xor_sync(0xFFFFFFFF, b2_0, off); ci2 = __shfl_xor_sync(0xFFFFFFFF, i2_0, off);
        {
            bool t = (c1 < b1_0) || (c1 == b1_0 && ci1 < i1_0);
            float w1 = t ? c1 : b1_0;  int wi1 = t ? ci1 : i1_0;
            float l1 = t ? b1_0 : c1;  int li1 = t ? i1_0 : ci1;
            bool u = (c2 < b2_0) || (c2 == b2_0 && ci2 < i2_0);
            float m2 = u ? c2 : b2_0;  int mi2 = u ? ci2 : i2_0;
            bool v = (l1 < m2) || (l1 == m2 && li1 < mi2);
            b1_0 = w1; i1_0 = wi1; b2_0 = v ? l1 : m2; i2_0 = v ? li1 : mi2;
        }
        // row 1 set
        c1 = __shfl_xor_sync(0xFFFFFFFF, b1_1, off); ci1 = __shfl_xor_sync(0xFFFFFFFF, i1_1, off);
        c2 = __shfl_xor_sync(0xFFFFFFFF, b2_1, off); ci2 = __shfl_xor_sync(0xFFFFFFFF, i2_1, off);
        {
            bool t = (c1 < b1_1) || (c1 == b1_1 && ci1 < i1_1);
            float w1 = t ? c1 : b1_1;  int wi1 = t ? ci1 : i1_1;
            float l1 = t ? b1_1 : c1;  int li1 = t ? i1_1 : ci1;
            bool u = (c2 < b2_1) || (c2 == b2_1 && ci2 < i2_1);
            float m2 = u ? c2 : b2_1;  int mi2 = u ? ci2 : i2_1;
            bool v = (l1 < m2) || (l1 == m2 && li1 < mi2);
            b1_1 = w1; i1_1 = wi1; b2_1 = v ? l1 : m2; i2_1 = v ? li1 : mi2;
        }
    }

    // ---- rescore (exact fp32) + pack + atomic merge across halves ----
    if ((lane & 3) == 0){
        int tok0 = n0 + wid*16 + (lane >> 2);
        int tok1 = tok0 + 8;
        {
            float d1 = exact_dd(z, emb, tok0, i1_0, zn0);
            int win = i1_0; float dw = d1;
            if (b2_0 - b1_0 < TH){
                float d2 = exact_dd(z, emb, tok0, i2_0, zn0);
                if (d2 < d1 || (d2 == d1 && i2_0 < i1_0)){ win = i2_0; dw = d2; }
            }
            atomicMin(&g_best[tok0], packbi(dw, win));
        }
        {
            float d1 = exact_dd(z, emb, tok1, i1_1, zn1);
            int win = i1_1; float dw = d1;
            if (b2_1 - b1_1 < TH){
                float d2 = exact_dd(z, emb, tok1, i2_1, zn1);
                if (d2 < d1 || (d2 == d1 && i2_1 < i1_1)){ win = i2_1; dw = d2; }
            }
            atomicMin(&g_best[tok1], packbi(dw, win));
        }
    }
}

// ---------------------------------------------------------------------------
// K3: gather z_q, straight-through output, loss partial, index output
// ---------------------------------------------------------------------------
__global__ void vq_out(const float* __restrict__ z, const float* __restrict__ emb,
                       float* __restrict__ outz, float* __restrict__ outIdxF, int writeF){
    int tid = threadIdx.x;
    int n0 = blockIdx.x * 64;
    const int b = n0 >> 12; const int hw0 = n0 & 4095;
    const float* zb = z    + b*262144 + hw0;
    float*       ob = outz + b*262144 + hw0;

    __shared__ int idxs[64];
    if (tid < 64){
        int idx = (int)(g_best[n0 + tid] & 0xFFFFFFFFull);
        idxs[tid] = idx;
        if (writeF) outIdxF[n0 + tid] = (float)idx;
    }
    __syncthreads();

    float ls = 0.f;
    for (int i = tid; i < 64*64; i += 256){
        int c = i >> 6, m = i & 63;
        float e  = __ldg(&emb[idxs[m]*64 + c]);
        float zv = zb[c*4096 + m];
        float t  = e - zv;
        ob[c*4096 + m] = zv + t;      // fl(zc + fl(zq - zc)) — STE rounding replicated
        ls = fmaf(t, t, ls);
    }
    __shared__ float red[256];
    red[tid] = ls; __syncthreads();
    for (int s = 128; s > 0; s >>= 1){
        if (tid < s) red[tid] += red[tid + s];
        __syncthreads();
    }
    if (tid == 0) atomicAdd(&g_loss, red[0]);
}

__global__ void vq_fin(float* __restrict__ out, int full){
    if (full){
        float m = g_loss * (1.f / (float)ZQ_ELEMS);
        out[ZQ_ELEMS] = m + 0.25f * m;
    }
}

// ---------------------------------------------------------------------------
extern "C" void kernel_launch(void* const* d_in, const int* in_sizes, int n_in,
                              void* d_out, int out_size){
    const float* z   = (const float*)d_in[0];
    const float* emb = (const float*)d_in[1];
    float* out = (float*)d_out;

    int full = (out_size >= ZQ_ELEMS + 1 + N_TOK) ? 1 : 0;

    cudaFuncSetAttribute(vq_main, cudaFuncAttributeMaxDynamicSharedMemorySize, SMEM_SZ);

    vq_pre<<<N_TOK/256, 256>>>(emb);
    dim3 grid(N_TOK/128, 2);
    vq_main<<<grid, NT, SMEM_SZ>>>(z, emb);
    vq_out<<<N_TOK/64, 256>>>(z, emb, out, full ? (out + ZQ_ELEMS + 1) : out, full);
    vq_fin<<<1, 1>>>(out, full);
}

// round 5
// speedup vs baseline: 1.0547x; 1.0002x over previous
#include <cuda_runtime.h>
#include <cstdint>

#define N_TOK    65536
#define KCODES   8192
#define DIM      64
#define ZQ_ELEMS 4194304     // 16*64*64*64
#define NT       256         // 8 warps
#define NCH      64          // 4096 codes per half / 64 per chunk
#define TH       1e-4f

// ---- dynamic smem layout (bytes) ----
#define SOFF_AP   0          // 65536 : A frags [w8][ks8][spl2][lane32][r4] fp32(tf32)
#define SOFF_BP   65536      // 65536 : B frags [buf2][nt8][ks8][spl2][lane32][slot2]
#define SOFF_EN   131072     // 2*64*4
#define SOFF_ZN   131584     // 128*4
#define SMEM_SZ   132096
// staging for z tile reuses the BP region (64*132*4 = 33792 <= 65536)

__device__ float              g_enorm[KCODES];
__device__ unsigned long long g_best[N_TOK];
__device__ float              g_loss;

__device__ __forceinline__ uint32_t tf32_rna(float v){
    uint32_t r; asm("cvt.rna.tf32.f32 %0, %1;" : "=r"(r) : "f"(v)); return r;
}
__device__ __forceinline__ void split_tf32(float v, uint32_t& hb, uint32_t& lb){
    hb = tf32_rna(v);
    lb = tf32_rna(v - __uint_as_float(hb));
}
__device__ __forceinline__ void mma_tf32(float* d, const uint32_t* a, const uint32_t* b){
    asm volatile("mma.sync.aligned.m16n8k8.row.col.f32.tf32.tf32.f32 "
        "{%0,%1,%2,%3}, {%4,%5,%6,%7}, {%8,%9}, {%0,%1,%2,%3};"
        : "+f"(d[0]), "+f"(d[1]), "+f"(d[2]), "+f"(d[3])
        : "r"(a[0]), "r"(a[1]), "r"(a[2]), "r"(a[3]), "r"(b[0]), "r"(b[1]));
}
__device__ __forceinline__ unsigned long long packbi(float dd, int idx){
    uint32_t u = __float_as_uint(dd);
    u = (u & 0x80000000u) ? ~u : (u | 0x80000000u);
    return ((unsigned long long)u << 32) | (uint32_t)idx;
}
// exact distance, replicating the validated R2 arithmetic bit-for-bit:
// sequential fmaf over d ascending; dd = fmaf(-2, dot, fl(zn+en))
__device__ float exact_dd(const float* __restrict__ z, const float* __restrict__ emb,
                          int tok, int k, float zn){
    int b = tok >> 12, hw = tok & 4095;
    const float* zp = z + b*262144 + hw;
    const float* ep = emb + k*64;
    float dot = 0.f;
    #pragma unroll
    for (int d = 0; d < 64; d++) dot = fmaf(__ldg(zp + d*4096), __ldg(ep + d), dot);
    float t2 = zn + __ldg(&g_enorm[k]);
    return fmaf(-2.f, dot, t2);
}

// ---------------------------------------------------------------------------
// K1: ||e_k||^2, init g_best, zero loss
// ---------------------------------------------------------------------------
__global__ void vq_pre(const float* __restrict__ emb){
    int t = blockIdx.x * 256 + threadIdx.x;
    if (t < KCODES){
        const float4* r = (const float4*)(emb + t*64);
        float s = 0.f;
        #pragma unroll
        for (int i = 0; i < 16; i++){
            float4 v = __ldg(&r[i]);
            s = fmaf(v.x,v.x,s); s = fmaf(v.y,v.y,s); s = fmaf(v.z,v.z,s); s = fmaf(v.w,v.w,s);
        }
        g_enorm[t] = s;
    }
    if (t < N_TOK) g_best[t] = 0xFFFFFFFFFFFFFFFFull;
    if (t == 0) g_loss = 0.f;
}

// ---------------------------------------------------------------------------
// K2: 3xTF32 mma.sync distance + top-2 argmin + exact rescore + atomic merge
// grid: (512 token tiles, 2 code halves); CTA = 128 tokens x 4096 codes
// ---------------------------------------------------------------------------
__global__ __launch_bounds__(NT, 1) void vq_main(const float* __restrict__ z,
                                                 const float* __restrict__ emb){
    extern __shared__ __align__(16) char smem[];
    float*    Ap  = (float*)(smem + SOFF_AP);
    float*    Bp  = (float*)(smem + SOFF_BP);
    float*    enS = (float*)(smem + SOFF_EN);
    float*    znS = (float*)(smem + SOFF_ZN);
    float*    stage = (float*)(smem + SOFF_BP);   // [64][132], pre-loop only

    int tid = threadIdx.x, wid = tid >> 5, lane = tid & 31;
    int n0 = blockIdx.x * 128;
    int kbase = blockIdx.y * 4096;
    const float* zb = z + (n0 >> 12) * 262144 + (n0 & 4095);

    // ---- stage z tile [d][m] (coalesced) ----
    for (int i = tid; i < 64*128; i += NT){
        int d = i >> 7, m = i & 127;
        stage[d*132 + m] = zb[d*4096 + m];
    }
    __syncthreads();
    // ---- zn (sequential fmaf d ascending — matches reference/R2) ----
    if (tid < 128){
        float s = 0.f;
        #pragma unroll
        for (int d = 0; d < 64; d++){ float v = stage[d*132 + tid]; s = fmaf(v, v, s); }
        znS[tid] = s;
    }
    __syncthreads();
    // ---- build A fragments (permuted, fragment-linear) ----
    // idx -> w, ks, spl, l, r ;  m = w*16 + l/4 + (r&1)*8 ; k = ks*8 + l%4 + ((r>>1)&1)*4
    for (int idx = tid; idx < 16384; idx += NT){
        int w = idx >> 11, rem = idx & 2047;
        int r = rem & 3, q = rem >> 2;
        int l = q & 31, p = q >> 5;
        int spl = p & 1, ks = p >> 1;
        int m = w*16 + (l >> 2) + (r & 1)*8;
        int k = ks*8 + (l & 3) + ((r >> 1) & 1)*4;
        float v = stage[k*132 + m];
        uint32_t hb = tf32_rna(v);
        uint32_t out = spl ? tf32_rna(v - __uint_as_float(hb)) : hb;
        // NOTE: stage overlaps Bp; A writes must not race stage reads of other threads
        ((uint32_t*)&Ap[0])[idx] = out;
    }
    __syncthreads();

    const float4* embc = (const float4*)emb;
    float zn0 = znS[wid*16 + (lane >> 2)];
    float zn1 = znS[wid*16 + (lane >> 2) + 8];

    // ---- B producer helper (inline) ----
    // chunk c -> buffer b. thread covers 4 float4 (16 elems), each elem -> hi/lo STS
    auto produce = [&](int c, int b){
        #pragma unroll
        for (int j = 0; j < 4; j++){
            int f = j*256 + tid;                       // float4 index in chunk
            float4 v = __ldg(&embc[(kbase + c*64)*16 + f]);
            int n = f >> 4, k0 = (f & 15) * 4;
            float vv[4] = {v.x, v.y, v.z, v.w};
            #pragma unroll
            for (int e = 0; e < 4; e++){
                int k = k0 + e;
                int nt = n >> 3, g = n & 7, ks = k >> 3, krel = k & 7;
                int t4 = krel & 3, slot = krel >> 2;
                int l = g*4 + t4;
                uint32_t hb, lb; split_tf32(vv[e], hb, lb);
                int w0 = b*8192 + (((nt*8 + ks)*2 + 0)*32 + l)*2 + slot;
                int w1 = b*8192 + (((nt*8 + ks)*2 + 1)*32 + l)*2 + slot;
                ((uint32_t*)Bp)[w0] = hb;
                ((uint32_t*)Bp)[w1] = lb;
            }
        }
        if (tid < 64) enS[b*64 + tid] = __ldg(&g_enorm[kbase + c*64 + tid]);
    };

    produce(0, 0);
    __syncthreads();

    float b1_0 = 3.402823e38f, b2_0 = 3.402823e38f;
    float b1_1 = 3.402823e38f, b2_1 = 3.402823e38f;
    int   i1_0 = 0, i2_0 = 0, i1_1 = 0, i2_1 = 0;

    #pragma unroll 1
    for (int c = 0; c < NCH; c++){
        int buf = c & 1;
        // prefetch next chunk into registers
        float4 pv[4];
        if (c + 1 < NCH){
            #pragma unroll
            for (int j = 0; j < 4; j++)
                pv[j] = __ldg(&embc[(kbase + (c+1)*64)*16 + j*256 + tid]);
        }

        // ---- mma over this chunk ----
        float acc[8][4];
        #pragma unroll
        for (int nt = 0; nt < 8; nt++){ acc[nt][0]=0.f; acc[nt][1]=0.f; acc[nt][2]=0.f; acc[nt][3]=0.f; }

        #pragma unroll
        for (int ks = 0; ks < 8; ks++){
            uint4 ah = *(const uint4*)&Ap[(wid*2048) + ((ks*2 + 0)*32 + lane)*4];
            uint4 al = *(const uint4*)&Ap[(wid*2048) + ((ks*2 + 1)*32 + lane)*4];
            #pragma unroll
            for (int nt = 0; nt < 8; nt++){
                uint2 bh = *(const uint2*)&Bp[buf*8192 + (((nt*8 + ks)*2 + 0)*32 + lane)*2];
                uint2 bl = *(const uint2*)&Bp[buf*8192 + (((nt*8 + ks)*2 + 1)*32 + lane)*2];
                mma_tf32(acc[nt], (const uint32_t*)&ah, (const uint32_t*)&bl);
                mma_tf32(acc[nt], (const uint32_t*)&al, (const uint32_t*)&bh);
                mma_tf32(acc[nt], (const uint32_t*)&ah, (const uint32_t*)&bh);
            }
        }

        // ---- epilogue: dd + top-2 update (ascending k within thread) ----
        int kb = kbase + c*64;
        #pragma unroll
        for (int nt = 0; nt < 8; nt++){
            #pragma unroll
            for (int e = 0; e < 2; e++){
                int col = nt*8 + (lane & 3)*2 + e;
                float en = enS[buf*64 + col];
                int kk = kb + col;
                float dd0 = fmaf(-2.f, acc[nt][e],     zn0 + en);
                float dd1 = fmaf(-2.f, acc[nt][e + 2], zn1 + en);
                if (dd0 < b1_0){ b2_0=b1_0; i2_0=i1_0; b1_0=dd0; i1_0=kk; }
                else if (dd0 < b2_0){ b2_0=dd0; i2_0=kk; }
                if (dd1 < b1_1){ b2_1=b1_1; i2_1=i1_1; b1_1=dd1; i1_1=kk; }
                else if (dd1 < b2_1){ b2_1=dd1; i2_1=kk; }
            }
        }

        // ---- store prefetched chunk into other buffer ----
        if (c + 1 < NCH){
            #pragma unroll
            for (int j = 0; j < 4; j++){
                int f = j*256 + tid;
                int n = f >> 4, k0 = (f & 15)*4;
                float vv[4] = {pv[j].x, pv[j].y, pv[j].z, pv[j].w};
                #pragma unroll
                for (int e = 0; e < 4; e++){
                    int k = k0 + e;
                    int nt = n >> 3, g = n & 7, ks = k >> 3, krel = k & 7;
                    int t4 = krel & 3, slot = krel >> 2;
                    int l = g*4 + t4;
                    uint32_t hb, lb; split_tf32(vv[e], hb, lb);
                    ((uint32_t*)Bp)[(buf^1)*8192 + (((nt*8+ks)*2+0)*32 + l)*2 + slot] = hb;
                    ((uint32_t*)Bp)[(buf^1)*8192 + (((nt*8+ks)*2+1)*32 + l)*2 + slot] = lb;
                }
            }
            if (tid < 64) enS[(buf^1)*64 + tid] = __ldg(&g_enorm[kbase + (c+1)*64 + tid]);
        }
        __syncthreads();
    }

    // ---- cross-thread top-2 merge within quad (rows owned by 4 lanes) ----
    #pragma unroll
    for (int off = 1; off <= 2; off <<= 1){
        float c1, c2; int ci1, ci2;
        // row 0 set
        c1 = __shfl_xor_sync(0xFFFFFFFF, b1_0, off); ci1 = __shfl_xor_sync(0xFFFFFFFF, i1_0, off);
        c2 = __shfl_xor_sync(0xFFFFFFFF, b2_0, off); ci2 = __shfl_xor_sync(0xFFFFFFFF, i2_0, off);
        {
            bool t = (c1 < b1_0) || (c1 == b1_0 && ci1 < i1_0);
            float w1 = t ? c1 : b1_0;  int wi1 = t ? ci1 : i1_0;
            float l1 = t ? b1_0 : c1;  int li1 = t ? i1_0 : ci1;
            bool u = (c2 < b2_0) || (c2 == b2_0 && ci2 < i2_0);
            float m2 = u ? c2 : b2_0;  int mi2 = u ? ci2 : i2_0;
            bool v = (l1 < m2) || (l1 == m2 && li1 < mi2);
            b1_0 = w1; i1_0 = wi1; b2_0 = v ? l1 : m2; i2_0 = v ? li1 : mi2;
        }
        // row 1 set
        c1 = __shfl_xor_sync(0xFFFFFFFF, b1_1, off); ci1 = __shfl_xor_sync(0xFFFFFFFF, i1_1, off);
        c2 = __shfl_xor_sync(0xFFFFFFFF, b2_1, off); ci2 = __shfl_xor_sync(0xFFFFFFFF, i2_1, off);
        {
            bool t = (c1 < b1_1) || (c1 == b1_1 && ci1 < i1_1);
            float w1 = t ? c1 : b1_1;  int wi1 = t ? ci1 : i1_1;
            float l1 = t ? b1_1 : c1;  int li1 = t ? i1_1 : ci1;
            bool u = (c2 < b2_1) || (c2 == b2_1 && ci2 < i2_1);
            float m2 = u ? c2 : b2_1;  int mi2 = u ? ci2 : i2_1;
            bool v = (l1 < m2) || (l1 == m2 && li1 < mi2);
            b1_1 = w1; i1_1 = wi1; b2_1 = v ? l1 : m2; i2_1 = v ? li1 : mi2;
        }
    }

    // ---- rescore (exact fp32) + pack + atomic merge across halves ----
    if ((lane & 3) == 0){
        int tok0 = n0 + wid*16 + (lane >> 2);
        int tok1 = tok0 + 8;
        {
            float d1 = exact_dd(z, emb, tok0, i1_0, zn0);
            int win = i1_0; float dw = d1;
            if (b2_0 - b1_0 < TH){
                float d2 = exact_dd(z, emb, tok0, i2_0, zn0);
                if (d2 < d1 || (d2 == d1 && i2_0 < i1_0)){ win = i2_0; dw = d2; }
            }
            atomicMin(&g_best[tok0], packbi(dw, win));
        }
        {
            float d1 = exact_dd(z, emb, tok1, i1_1, zn1);
            int win = i1_1; float dw = d1;
            if (b2_1 - b1_1 < TH){
                float d2 = exact_dd(z, emb, tok1, i2_1, zn1);
                if (d2 < d1 || (d2 == d1 && i2_1 < i1_1)){ win = i2_1; dw = d2; }
            }
            atomicMin(&g_best[tok1], packbi(dw, win));
        }
    }
}

// ---------------------------------------------------------------------------
// K3: gather z_q, straight-through output, loss partial, index output
// ---------------------------------------------------------------------------
__global__ void vq_out(const float* __restrict__ z, const float* __restrict__ emb,
                       float* __restrict__ outz, float* __restrict__ outIdxF, int writeF){
    int tid = threadIdx.x;
    int n0 = blockIdx.x * 64;
    const int b = n0 >> 12; const int hw0 = n0 & 4095;
    const float* zb = z    + b*262144 + hw0;
    float*       ob = outz + b*262144 + hw0;

    __shared__ int idxs[64];
    if (tid < 64){
        int idx = (int)(g_best[n0 + tid] & 0xFFFFFFFFull);
        idxs[tid] = idx;
        if (writeF) outIdxF[n0 + tid] = (float)idx;
    }
    __syncthreads();

    float ls = 0.f;
    for (int i = tid; i < 64*64; i += 256){
        int c = i >> 6, m = i & 63;
        float e  = __ldg(&emb[idxs[m]*64 + c]);
        float zv = zb[c*4096 + m];
        float t  = e - zv;
        ob[c*4096 + m] = zv + t;      // fl(zc + fl(zq - zc)) — STE rounding replicated
        ls = fmaf(t, t, ls);
    }
    __shared__ float red[256];
    red[tid] = ls; __syncthreads();
    for (int s = 128; s > 0; s >>= 1){
        if (tid < s) red[tid] += red[tid + s];
        __syncthreads();
    }
    if (tid == 0) atomicAdd(&g_loss, red[0]);
}

__global__ void vq_fin(float* __restrict__ out, int full){
    if (full){
        float m = g_loss * (1.f / (float)ZQ_ELEMS);
        out[ZQ_ELEMS] = m + 0.25f * m;
    }
}

// ---------------------------------------------------------------------------
extern "C" void kernel_launch(void* const* d_in, const int* in_sizes, int n_in,
                              void* d_out, int out_size){
    const float* z   = (const float*)d_in[0];
    const float* emb = (const float*)d_in[1];
    float* out = (float*)d_out;

    int full = (out_size >= ZQ_ELEMS + 1 + N_TOK) ? 1 : 0;

    cudaFuncSetAttribute(vq_main, cudaFuncAttributeMaxDynamicSharedMemorySize, SMEM_SZ);

    vq_pre<<<N_TOK/256, 256>>>(emb);
    dim3 grid(N_TOK/128, 2);
    vq_main<<<grid, NT, SMEM_SZ>>>(z, emb);
    vq_out<<<N_TOK/64, 256>>>(z, emb, out, full ? (out + ZQ_ELEMS + 1) : out, full);
    vq_fin<<<1, 1>>>(out, full);
}

// round 6
// speedup vs baseline: 2.7923x; 2.6475x over previous
#include <cuda_runtime.h>
#include <cstdint>

#define N_TOK    65536
#define KCODES   8192
#define ZQ_ELEMS 4194304
#define NT       256
#define NCH      64          // 4096 codes per half / 64 per chunk
#define ACC_TH   0.4096f     // 1e-4 (dd domain) * 4096 (acc domain)
#define FLT_BIG  3.402823e38f

// ---- smem layout (bytes) ----
#define SOFF_Z   0           // 32768 : z tile [d64][m128] fp32 (kept live for rescore)
#define SOFF_B   32768       // 16896 : B frags [buf2][(nt4+ks)*33 + L] uint2 (padded)
#define SOFF_EN  49664       // 2*64*4
#define SOFF_ZN  50176       // 128*4
#define SMEM_SZ  50688
#define BSTRIDE  2112        // uint32 units per buffer (8*4*33*2)

__device__ float              g_enorm[KCODES];
__device__ unsigned long long g_best[N_TOK];
__device__ float              g_loss;

__device__ __forceinline__ uint32_t pack2h(float lo, float hi){
    uint32_t r; asm("cvt.rn.f16x2.f32 %0, %1, %2;" : "=r"(r) : "f"(hi), "f"(lo)); return r;
}
__device__ __forceinline__ void mma_fp16(float* d, const uint32_t* a, uint32_t b0, uint32_t b1){
    asm volatile("mma.sync.aligned.m16n8k16.row.col.f32.f16.f16.f32 "
        "{%0,%1,%2,%3}, {%4,%5,%6,%7}, {%8,%9}, {%0,%1,%2,%3};"
        : "+f"(d[0]), "+f"(d[1]), "+f"(d[2]), "+f"(d[3])
        : "r"(a[0]), "r"(a[1]), "r"(a[2]), "r"(a[3]), "r"(b0), "r"(b1));
}
__device__ __forceinline__ unsigned long long packbi(float dd, int idx){
    uint32_t u = __float_as_uint(dd);
    u = (u & 0x80000000u) ? ~u : (u | 0x80000000u);
    return ((unsigned long long)u << 32) | (uint32_t)idx;
}

// ---------------------------------------------------------------------------
// K1: ||e_k||^2 (sequential fmaf, d ascending — matches reference rounding),
//     init g_best, zero loss
// ---------------------------------------------------------------------------
__global__ void vq_pre(const float* __restrict__ emb){
    int t = blockIdx.x * 256 + threadIdx.x;
    if (t < KCODES){
        const float4* r = (const float4*)(emb + t*64);
        float s = 0.f;
        #pragma unroll
        for (int i = 0; i < 16; i++){
            float4 v = __ldg(&r[i]);
            s = fmaf(v.x,v.x,s); s = fmaf(v.y,v.y,s); s = fmaf(v.z,v.z,s); s = fmaf(v.w,v.w,s);
        }
        g_enorm[t] = s;
    }
    if (t < N_TOK) g_best[t] = 0xFFFFFFFFFFFFFFFFull;
    if (t == 0) g_loss = 0.f;
}

// ---------------------------------------------------------------------------
// K2: fp16 mma (B scaled 2^13), acc-domain argmax top-3 + exact fp32 rescore.
// grid (512 token tiles, 2 code halves); CTA = 128 tokens x 4096 codes.
// ---------------------------------------------------------------------------
__global__ __launch_bounds__(NT, 2) void vq_main(const float* __restrict__ z,
                                                 const float* __restrict__ emb){
    extern __shared__ __align__(16) char smem[];
    float*    zS  = (float*)(smem + SOFF_Z);        // [64][128]
    uint32_t* Bs  = (uint32_t*)(smem + SOFF_B);
    float*    enS = (float*)(smem + SOFF_EN);       // [2][64]
    float*    znS = (float*)(smem + SOFF_ZN);       // [128]

    int tid = threadIdx.x, wid = tid >> 5, lane = tid & 31;
    int n0 = blockIdx.x * 128;
    int kbase = blockIdx.y * 4096;
    const float* zb = z + (n0 >> 12) * 262144 + (n0 & 4095);

    // ---- stage z tile [d][m] (coalesced) ----
    for (int i = tid; i < 64*128; i += NT){
        int d = i >> 7, m = i & 127;
        zS[d*128 + m] = zb[d*4096 + m];
    }
    __syncthreads();

    // ---- zn (sequential fmaf, d ascending) ----
    if (tid < 128){
        float s = 0.f;
        #pragma unroll
        for (int d = 0; d < 64; d++){ float v = zS[d*128 + tid]; s = fmaf(v, v, s); }
        znS[tid] = s;
    }

    // ---- A fragments in registers (loop-invariant) ----
    uint32_t Af[4][4];
    {
        int r0 = wid*16 + (lane >> 2);
        #pragma unroll
        for (int ks = 0; ks < 4; ks++){
            int k0 = ks*16 + (lane & 3)*2;
            Af[ks][0] = pack2h(zS[(k0  )*128 + r0  ], zS[(k0+1)*128 + r0  ]);
            Af[ks][1] = pack2h(zS[(k0  )*128 + r0+8], zS[(k0+1)*128 + r0+8]);
            Af[ks][2] = pack2h(zS[(k0+8)*128 + r0  ], zS[(k0+9)*128 + r0  ]);
            Af[ks][3] = pack2h(zS[(k0+8)*128 + r0+8], zS[(k0+9)*128 + r0+8]);
        }
    }

    // ---- produce chunk 0 into buffer 0 ----
    {
        const float4* src = (const float4*)(emb + (size_t)(kbase)*64);
        #pragma unroll
        for (int j = 0; j < 4; j++){
            int f = j*256 + tid;
            float4 v = __ldg(&src[f]);
            int n = f >> 4, k0 = (f & 15)*4;
            uint32_t u0 = pack2h(v.x*8192.f, v.y*8192.f);
            uint32_t u1 = pack2h(v.z*8192.f, v.w*8192.f);
            int nt = n >> 3, ks = k0 >> 4, p = (k0 >> 3) & 1;
            int Lt = (n & 7)*4 + ((k0 & 7) >> 1);
            uint32_t* dst = Bs + ((nt*4 + ks)*33 + Lt)*2 + p;
            dst[0] = u0; dst[2] = u1;
        }
        if (tid < 64) enS[tid] = __ldg(&g_enorm[kbase + tid]);
    }
    __syncthreads();

    // ---- top-3 (acc domain: larger = better), per thread, 2 rows ----
    float s1_0 = -FLT_BIG, s2_0 = -FLT_BIG, s3_0 = -FLT_BIG;
    float s1_1 = -FLT_BIG, s2_1 = -FLT_BIG, s3_1 = -FLT_BIG;
    int   i1_0 = 0, i2_0 = 0, i3_0 = 0, i1_1 = 0, i2_1 = 0, i3_1 = 0;

    #pragma unroll 1
    for (int c = 0; c < NCH; c++){
        int buf = c & 1;
        // prefetch next chunk
        float4 pv[4];
        bool more = (c + 1 < NCH);
        if (more){
            const float4* src = (const float4*)(emb + (size_t)(kbase + (c+1)*64)*64);
            #pragma unroll
            for (int j = 0; j < 4; j++) pv[j] = __ldg(&src[j*256 + tid]);
        }

        // acc init: -4096 * enorm  (key = en - 2dot = -acc * 2^-12; argmin d == argmax acc)
        float acc[8][4];
        #pragma unroll
        for (int nt = 0; nt < 8; nt++){
            int c0 = nt*8 + (lane & 3)*2;
            float2 en2 = *(const float2*)&enS[buf*64 + c0];
            acc[nt][0] = en2.x * -4096.f; acc[nt][1] = en2.y * -4096.f;
            acc[nt][2] = acc[nt][0];      acc[nt][3] = acc[nt][1];
        }

        const uint32_t* Bb = Bs + buf*BSTRIDE;
        #pragma unroll
        for (int ks = 0; ks < 4; ks++){
            #pragma unroll
            for (int nt = 0; nt < 8; nt++){
                uint2 b = *(const uint2*)(Bb + ((nt*4 + ks)*33 + lane)*2);
                mma_fp16(acc[nt], Af[ks], b.x, b.y);
            }
        }

        // epilogue: pairwise max + rare top-3 insert (ascending code order)
        int kk0 = kbase + c*64;
        #pragma unroll
        for (int nt = 0; nt < 8; nt++){
            int c0 = nt*8 + (lane & 3)*2;
            int kA = kk0 + c0, kB = kA + 1;
            // row 0
            {
                float a = acc[nt][0], b2 = acc[nt][1];
                if (fmaxf(a, b2) > s3_0){
                    if (a > s1_0){ s3_0=s2_0;i3_0=i2_0; s2_0=s1_0;i2_0=i1_0; s1_0=a;i1_0=kA; }
                    else if (a > s2_0){ s3_0=s2_0;i3_0=i2_0; s2_0=a;i2_0=kA; }
                    else if (a > s3_0){ s3_0=a;i3_0=kA; }
                    if (b2 > s1_0){ s3_0=s2_0;i3_0=i2_0; s2_0=s1_0;i2_0=i1_0; s1_0=b2;i1_0=kB; }
                    else if (b2 > s2_0){ s3_0=s2_0;i3_0=i2_0; s2_0=b2;i2_0=kB; }
                    else if (b2 > s3_0){ s3_0=b2;i3_0=kB; }
                }
            }
            // row 1
            {
                float a = acc[nt][2], b2 = acc[nt][3];
                if (fmaxf(a, b2) > s3_1){
                    if (a > s1_1){ s3_1=s2_1;i3_1=i2_1; s2_1=s1_1;i2_1=i1_1; s1_1=a;i1_1=kA; }
                    else if (a > s2_1){ s3_1=s2_1;i3_1=i2_1; s2_1=a;i2_1=kA; }
                    else if (a > s3_1){ s3_1=a;i3_1=kA; }
                    if (b2 > s1_1){ s3_1=s2_1;i3_1=i2_1; s2_1=s1_1;i2_1=i1_1; s1_1=b2;i1_1=kB; }
                    else if (b2 > s2_1){ s3_1=s2_1;i3_1=i2_1; s2_1=b2;i2_1=kB; }
                    else if (b2 > s3_1){ s3_1=b2;i3_1=kB; }
                }
            }
        }

        // store prefetched chunk into other buffer
        if (more){
            uint32_t* BW = Bs + (buf^1)*BSTRIDE;
            #pragma unroll
            for (int j = 0; j < 4; j++){
                int f = j*256 + tid;
                int n = f >> 4, k0 = (f & 15)*4;
                uint32_t u0 = pack2h(pv[j].x*8192.f, pv[j].y*8192.f);
                uint32_t u1 = pack2h(pv[j].z*8192.f, pv[j].w*8192.f);
                int nt = n >> 3, ks = k0 >> 4, p = (k0 >> 3) & 1;
                int Lt = (n & 7)*4 + ((k0 & 7) >> 1);
                uint32_t* dst = BW + ((nt*4 + ks)*33 + Lt)*2 + p;
                dst[0] = u0; dst[2] = u1;
            }
            if (tid < 64) enS[(buf^1)*64 + tid] = __ldg(&g_enorm[kbase + (c+1)*64 + tid]);
        }
        __syncthreads();
    }

    // ---- quad max, then exact fp32 rescore of qualifying top-3 candidates ----
    float q0 = s1_0, q1 = s1_1;
    #pragma unroll
    for (int off = 1; off <= 2; off <<= 1){
        q0 = fmaxf(q0, __shfl_xor_sync(0xFFFFFFFF, q0, off));
        q1 = fmaxf(q1, __shfl_xor_sync(0xFFFFFFFF, q1, off));
    }
    float thr0 = q0 - ACC_TH, thr1 = q1 - ACC_TH;
    int r0 = wid*16 + (lane >> 2);

    auto rescore = [&](int rloc, float sv, int idx, float thr, float zn){
        if (sv >= thr){
            const float* ep = emb + idx*64;
            float dot = 0.f;
            #pragma unroll
            for (int d = 0; d < 64; d++) dot = fmaf(zS[d*128 + rloc], __ldg(ep + d), dot);
            float dd = fmaf(-2.f, dot, zn + __ldg(&g_enorm[idx]));   // exact (R2-validated) formula
            atomicMin(&g_best[n0 + rloc], packbi(dd, idx));
        }
    };
    float zn0 = znS[r0], zn1 = znS[r0 + 8];
    rescore(r0,     s1_0, i1_0, thr0, zn0);
    rescore(r0,     s2_0, i2_0, thr0, zn0);
    rescore(r0,     s3_0, i3_0, thr0, zn0);
    rescore(r0 + 8, s1_1, i1_1, thr1, zn1);
    rescore(r0 + 8, s2_1, i2_1, thr1, zn1);
    rescore(r0 + 8, s3_1, i3_1, thr1, zn1);
}

// ---------------------------------------------------------------------------
// K3: gather z_q, straight-through output, loss partial, index output
// ---------------------------------------------------------------------------
__global__ void vq_out(const float* __restrict__ z, const float* __restrict__ emb,
                       float* __restrict__ outz, float* __restrict__ outIdxF, int writeF){
    int tid = threadIdx.x;
    int n0 = blockIdx.x * 64;
    const int b = n0 >> 12; const int hw0 = n0 & 4095;
    const float* zb = z    + b*262144 + hw0;
    float*       ob = outz + b*262144 + hw0;

    __shared__ int idxs[64];
    if (tid < 64){
        int idx = (int)(g_best[n0 + tid] & 0xFFFFFFFFull);
        idxs[tid] = idx;
        if (writeF) outIdxF[n0 + tid] = (float)idx;
    }
    __syncthreads();

    float ls = 0.f;
    for (int i = tid; i < 64*64; i += 256){
        int c = i >> 6, m = i & 63;
        float e  = __ldg(&emb[idxs[m]*64 + c]);
        float zv = zb[c*4096 + m];
        float t  = e - zv;
        ob[c*4096 + m] = zv + t;      // fl(zc + fl(zq - zc)) — STE rounding replicated
        ls = fmaf(t, t, ls);
    }
    __shared__ float red[256];
    red[tid] = ls; __syncthreads();
    for (int s = 128; s > 0; s >>= 1){
        if (tid < s) red[tid] += red[tid + s];
        __syncthreads();
    }
    if (tid == 0) atomicAdd(&g_loss, red[0]);
}

__global__ void vq_fin(float* __restrict__ out, int full){
    if (full){
        float m = g_loss * (1.f / (float)ZQ_ELEMS);
        out[ZQ_ELEMS] = m + 0.25f * m;
    }
}

// ---------------------------------------------------------------------------
extern "C" void kernel_launch(void* const* d_in, const int* in_sizes, int n_in,
                              void* d_out, int out_size){
    const float* z   = (const float*)d_in[0];
    const float* emb = (const float*)d_in[1];
    float* out = (float*)d_out;

    int full = (out_size >= ZQ_ELEMS + 1 + N_TOK) ? 1 : 0;

    cudaFuncSetAttribute(vq_main, cudaFuncAttributeMaxDynamicSharedMemorySize, SMEM_SZ);

    vq_pre<<<N_TOK/256, 256>>>(emb);
    dim3 grid(N_TOK/128, 2);
    vq_main<<<grid, NT, SMEM_SZ>>>(z, emb);
    vq_out<<<N_TOK/64, 256>>>(z, emb, out, full ? (out + ZQ_ELEMS + 1) : out, full);
    vq_fin<<<1, 1>>>(out, full);
}